// round 5
// baseline (speedup 1.0000x reference)
#include <cuda_runtime.h>
#include <math.h>

#define N_    256
#define B_    64
#define FIN   5
#define NE_   65536

// ---------------- scratch (no allocations allowed) ----------------
__device__ __align__(16) float g_S[4 * NE_];   // S0, SA, S1, S2  (0.1I + 0.45*M)
__device__ __align__(16) float g_P[NE_];       // P  = S0*SA
__device__ __align__(16) float g_G[2 * NE_];   // K1 = P*S1,  K2 = SA*S2
__device__ float g_dis[N_];
__device__ float g_logits[3];

// ---------------- packed f32x2 helpers ----------------
static __device__ __forceinline__ unsigned long long ffma2(unsigned long long a,
                                                           unsigned long long b,
                                                           unsigned long long c) {
    unsigned long long d;
    asm("fma.rn.f32x2 %0, %1, %2, %3;" : "=l"(d) : "l"(a), "l"(b), "l"(c));
    return d;
}
static __device__ __forceinline__ unsigned long long fadd2(unsigned long long a,
                                                           unsigned long long b) {
    unsigned long long d;
    asm("add.rn.f32x2 %0, %1, %2;" : "=l"(d) : "l"(a), "l"(b));
    return d;
}
static __device__ __forceinline__ unsigned long long dup2(float v) {
    unsigned long long d;
    unsigned int u = __float_as_uint(v);
    asm("mov.b64 %0, {%1, %1};" : "=l"(d) : "r"(u));
    return d;
}
static __device__ __forceinline__ float2 unpack2(unsigned long long v) {
    unsigned int lo, hi;
    asm("mov.b64 {%0, %1}, %2;" : "=r"(lo), "=r"(hi) : "l"(v));
    return make_float2(__uint_as_float(lo), __uint_as_float(hi));
}

// ---------------- digamma (fp32) ----------------
static __device__ float digamma_f(float x) {
    float r = 0.0f;
    while (x < 8.0f) { r -= __fdividef(1.0f, x); x += 1.0f; }
    float f = __fdividef(1.0f, x * x);
    float s = f * (1.0f / 12.0f - f * (1.0f / 120.0f - f * (1.0f / 252.0f
            - f * (1.0f / 240.0f - f * (1.0f / 132.0f)))));
    return r + logf(x) - 0.5f / x - s;
}

// ---------------- kernel 1: degree/dis (32 blocks) + scalar block (block 32) --
__global__ void __launch_bounds__(256) deg_scalar_kernel(
        const float* __restrict__ ewp,
        const float* __restrict__ a_uc,
        const float* __restrict__ b_uc,
        const float* __restrict__ u_pi,
        float* __restrict__ out) {
    int b = blockIdx.x, t = threadIdx.x;
    if (b == 32) {   // scalar-only block (fp32)
        __shared__ float kld_s[3];
        if (t < 3) {
            int l = t;
            float au = a_uc[l]; if (au < -10.0f) au = -10.0f;
            float bu = b_uc[l]; if (bu < -10.0f) bu = -10.0f; if (bu > 50.0f) bu = 50.0f;
            float a = log1pf(expf(au));
            float bb = log1pf(expf(bu));
            float up = u_pi[l];
            up = fminf(fmaxf(up, 1e-6f), 1.0f - 1e-6f);
            float pi = powf(1.0f - powf(up, 1.0f / bb), 1.0f / a);
            g_logits[l] = logf(pi) - log1pf(-pi);
            out[193 + l] = pi;   // drop_rates
            const float euler = 0.577215664901532f;
            kld_s[l] = (1.0f - 0.8f / a) * (-euler - digamma_f(bb) - 1.0f / bb)
                     + logf(a * bb + 1e-10f) - logf(0.8f) - (bb - 1.0f) / bb;
        }
        __syncthreads();
        if (t == 0) out[192] = kld_s[0] + kld_s[1] + kld_s[2];   // kld_loss
        return;
    }
    // degree: warp w handles row r = b*8+w
    int w = t >> 5, l = t & 31;
    int r = b * 8 + w;
    float s = 0.f;
    #pragma unroll
    for (int jj = 0; jj < 8; jj++) {
        int j = l + jj * 32;
        int hi = max(r, j), lo = min(r, j);
        s += fabsf(ewp[(hi * (hi + 1)) / 2 + lo]);
    }
    #pragma unroll
    for (int o = 16; o > 0; o >>= 1) s += __shfl_xor_sync(0xffffffffu, s, o);
    if (l == 0) g_dis[r] = (s > 0.f) ? rsqrtf(s) : 0.f;
}

// ---------------- kernel 2: build S matrices (0.1I + 0.45*M) ------------------
__global__ void __launch_bounds__(256) mats_kernel(const float* __restrict__ ewp,
                                                   const float* __restrict__ u_rb) {
    int i = blockIdx.x, j = threadIdx.x;
    int r = max(i, j), c = min(i, j);
    float w = ewp[(r * (r + 1)) / 2 + c];
    float aij = g_dis[i] * w * g_dis[j];
    int e = i * N_ + j;
    float diag = (i == j) ? 0.1f : 0.0f;
    g_S[1 * NE_ + e] = 0.45f * aij + diag;                        // SA
    #pragma unroll
    for (int l = 0; l < 3; l++) {
        float ur = u_rb[l * NE_ + e];
        ur = fminf(fmaxf(ur, 1e-6f), 1.0f - 1e-6f);
        float tt = (g_logits[l] + __logf(ur) - __logf(1.0f - ur)) * (1.0f / 0.6f);
        float z = __fdividef(1.0f, 1.0f + __expf(-tt));
        int slot = (l == 0) ? 0 : (l + 1);                        // S0, S1, S2
        g_S[slot * NE_ + e] = 0.45f * z * aij + diag;
    }
}

// ---------------- kernel 3: 256x256x256 fp32 GEMM (tile 32x32, dual) ----------
// grid 128 -> two GEMMs (bx>>6 selects triple); grid 64 -> triple 0 only.
#define GEMM_SMEM (33280 + 32768)
__global__ void __launch_bounds__(256) gemm_kernel(
        const float* __restrict__ A0, const float* __restrict__ B0, float* __restrict__ C0,
        const float* __restrict__ A1, const float* __restrict__ B1, float* __restrict__ C1) {
    extern __shared__ __align__(16) char gsm[];
    float*  As = (float*)gsm;                 // [32][260] padded
    float4* Bs = (float4*)(gsm + 33280);      // [256][8]

    int bx = blockIdx.x;
    int g = bx >> 6, tile = bx & 63;
    const float* A = g ? A1 : A0;
    const float* B = g ? B1 : B0;
    float*       C = g ? C1 : C0;
    int tr = tile >> 3, tc = tile & 7;
    int t = threadIdx.x;

    // load A strip (rows tr*32..+31, full K) and B strip (full K, cols tc*32..+31)
    #pragma unroll
    for (int it = 0; it < 8; it++) {
        int idx = t + it * 256;               // 2048 float4s each
        int r = idx >> 6, k4 = (idx & 63) << 2;
        *(float4*)&As[r * 260 + k4] = *(const float4*)&A[(tr * 32 + r) * 256 + k4];
        int rowk = idx >> 3, c4 = idx & 7;
        Bs[rowk * 8 + c4] = *(const float4*)&B[rowk * 256 + tc * 32 + c4 * 4];
    }
    __syncthreads();

    int r = t >> 3, c8 = t & 7;
    unsigned long long acc0 = 0ull, acc1 = 0ull;
    const float* arow = &As[r * 260];
    #pragma unroll 4
    for (int k = 0; k < 256; k++) {
        unsigned long long a = dup2(arow[k]);
        ulonglong2 bv = *(const ulonglong2*)&Bs[k * 8 + c8];
        acc0 = ffma2(a, bv.x, acc0);
        acc1 = ffma2(a, bv.y, acc1);
    }
    float2 a0 = unpack2(acc0), a1 = unpack2(acc1);
    float4 res = make_float4(a0.x, a0.y, a1.x, a1.y);
    *(float4*)&C[(tr * 32 + r) * 256 + tc * 32 + c8 * 4] = res;
}

// ---------------- kernel 4: 2-stage conv + head, clustered --------------------
// 128 blocks = (graph b = blockIdx.x>>1, column half c = blockIdx.x&1),
// cluster (2,1,1), 512 threads. Stage 0: x3 = relu(K1^T x); stage 1: o = K2^T x3.
// K slabs stream via cp.async double-buffered halves; cluster exchanges x3.
#define SM_MTILE   0          // 2 * 128*128 f32 = 131072
#define SM_XD      131072     // 256*6 u64       = 12288
#define SM_XP      143360     // 256*5 f32       = 5120
#define SM_PS      148480     // 512*11 u64      = 45056
#define SM_POOL    193536     // 512 f32         = 2048
#define SM_POOLP   195584     // 128 f32         = 512
#define SM_TOTAL   196096

__global__ void __launch_bounds__(512, 1) __cluster_dims__(2, 1, 1)
conv_head_kernel(const float* __restrict__ x,
                 const float* __restrict__ lin_w, const float* __restrict__ lin_b,
                 const float* __restrict__ fc_w,  const float* __restrict__ fc_b,
                 float* __restrict__ out) {
    extern __shared__ __align__(16) char sm_[];
    float*              Mtile = (float*)(sm_ + SM_MTILE);
    unsigned long long* Xd    = (unsigned long long*)(sm_ + SM_XD);
    float*              Xp    = (float*)(sm_ + SM_XP);
    unsigned long long* Ps    = (unsigned long long*)(sm_ + SM_PS);
    float*              Pool  = (float*)(sm_ + SM_POOL);
    float*              PoolP = (float*)(sm_ + SM_POOLP);

    const int t  = threadIdx.x;
    const int j4 = t & 31;              // 4-col group within the 128-col slab
    const int q  = t >> 5;              // 0..15 K-split (8 rows per half)
    const int b  = blockIdx.x >> 1;
    const int c  = blockIdx.x & 1;      // == cluster rank
    const unsigned prank = (unsigned)(c ^ 1);

    auto issue_half = [&](const float* gsrc, float* stile) {
        #pragma unroll
        for (int k = 0; k < 8; k++) {
            int o = (k << 9) + t;
            int row = o >> 5, seg = (o & 31) << 2;
            const float* src = gsrc + row * 256 + seg;
            unsigned int dst = (unsigned int)__cvta_generic_to_shared(&stile[row * 128 + seg]);
            asm volatile("cp.async.cg.shared.global [%0], [%1], 16;" :: "r"(dst), "l"(src));
        }
        asm volatile("cp.async.commit_group;" ::: "memory");
    };

    // prefetch stage 0 (K1)
    {
        const float* g0 = g_G + 0 * NE_ + c * 128;
        issue_half(g0, Mtile);
        issue_half(g0 + 128 * 256, Mtile + 16384);
    }

    // load this graph's X
    {
        const float* xb = x + b * (N_ * FIN);
        for (int idx = t; idx < N_ * FIN; idx += 512) {
            float v = xb[idx];
            int i = idx / 5, f = idx - i * 5;
            Xp[idx] = v;
            Xd[i * 6 + f] = dup2(v);
        }
    }

    unsigned int peerXp, peerXd;
    {
        unsigned int lxp = (unsigned int)__cvta_generic_to_shared(Xp);
        unsigned int lxd = (unsigned int)__cvta_generic_to_shared(Xd);
        asm("mapa.shared::cluster.u32 %0, %1, %2;" : "=r"(peerXp) : "r"(lxp), "r"(prank));
        asm("mapa.shared::cluster.u32 %0, %1, %2;" : "=r"(peerXd) : "r"(lxd), "r"(prank));
    }

    unsigned long long accA[FIN], accB[FIN];
    const int qq8 = q * 8;

    #pragma unroll 1
    for (int cs = 0; cs < 2; cs++) {
        #pragma unroll
        for (int f = 0; f < FIN; f++) { accA[f] = 0ull; accB[f] = 0ull; }

        asm volatile("cp.async.wait_group 1;" ::: "memory");
        __syncthreads();

        #pragma unroll
        for (int r_ = 0; r_ < 8; r_++) {
            int row = qq8 + r_;
            ulonglong2 mv = *(const ulonglong2*)&Mtile[row * 128 + j4 * 4];
            const unsigned long long* xr = &Xd[row * 6];
            ulonglong2 x01 = *(const ulonglong2*)xr;
            ulonglong2 x23 = *(const ulonglong2*)(xr + 2);
            unsigned long long x4 = xr[4];
            accA[0] = ffma2(mv.x, x01.x, accA[0]);  accB[0] = ffma2(mv.y, x01.x, accB[0]);
            accA[1] = ffma2(mv.x, x01.y, accA[1]);  accB[1] = ffma2(mv.y, x01.y, accB[1]);
            accA[2] = ffma2(mv.x, x23.x, accA[2]);  accB[2] = ffma2(mv.y, x23.x, accB[2]);
            accA[3] = ffma2(mv.x, x23.y, accA[3]);  accB[3] = ffma2(mv.y, x23.y, accB[3]);
            accA[4] = ffma2(mv.x, x4,    accA[4]);  accB[4] = ffma2(mv.y, x4,    accB[4]);
        }

        asm volatile("cp.async.wait_group 0;" ::: "memory");
        __syncthreads();

        #pragma unroll
        for (int r_ = 0; r_ < 8; r_++) {
            int row = qq8 + r_;
            ulonglong2 mv = *(const ulonglong2*)&Mtile[16384 + row * 128 + j4 * 4];
            const unsigned long long* xr = &Xd[(128 + row) * 6];
            ulonglong2 x01 = *(const ulonglong2*)xr;
            ulonglong2 x23 = *(const ulonglong2*)(xr + 2);
            unsigned long long x4 = xr[4];
            accA[0] = ffma2(mv.x, x01.x, accA[0]);  accB[0] = ffma2(mv.y, x01.x, accB[0]);
            accA[1] = ffma2(mv.x, x01.y, accA[1]);  accB[1] = ffma2(mv.y, x01.y, accB[1]);
            accA[2] = ffma2(mv.x, x23.x, accA[2]);  accB[2] = ffma2(mv.y, x23.x, accB[2]);
            accA[3] = ffma2(mv.x, x23.y, accA[3]);  accB[3] = ffma2(mv.y, x23.y, accB[3]);
            accA[4] = ffma2(mv.x, x4,    accA[4]);  accB[4] = ffma2(mv.y, x4,    accB[4]);
        }

        {
            int base = (q * 32 + j4) * 11;
            #pragma unroll
            for (int f = 0; f < FIN; f++) { Ps[base + f] = accA[f]; Ps[base + 5 + f] = accB[f]; }
        }
        __syncthreads();   // done reading Mtile & writing Ps

        // prefetch stage 1 (K2)
        if (cs == 0) {
            const float* gsrc = g_G + 1 * NE_ + c * 128;
            issue_half(gsrc, Mtile);
            issue_half(gsrc + 128 * 256, Mtile + 16384);
        }

        // combine 16 K-splits; stage 0: relu + local+peer update; stage 1: local only
        if (t < 320) {
            int f = t % 5, pc = t / 5;
            int j4c = pc >> 1, a = pc & 1;
            unsigned long long s = Ps[j4c * 11 + a * 5 + f];
            #pragma unroll
            for (int qq = 1; qq < 16; qq++)
                s = fadd2(s, Ps[(qq * 32 + j4c) * 11 + a * 5 + f]);
            float2 sv = unpack2(s);
            float y0 = sv.x, y1 = sv.y;
            if (cs == 0) { y0 = fmaxf(y0, 0.f); y1 = fmaxf(y1, 0.f); }
            int g0c = c * 128 + 4 * j4c + 2 * a;
            Xp[g0c * 5 + f] = y0;  Xp[(g0c + 1) * 5 + f] = y1;
            if (cs == 0) {
                unsigned long long d0 = dup2(y0), d1 = dup2(y1);
                Xd[g0c * 6 + f] = d0;  Xd[(g0c + 1) * 6 + f] = d1;
                asm volatile("st.shared::cluster.f32 [%0], %1;" :: "r"(peerXp + (g0c * 5 + f) * 4), "f"(y0));
                asm volatile("st.shared::cluster.f32 [%0], %1;" :: "r"(peerXp + ((g0c + 1) * 5 + f) * 4), "f"(y1));
                asm volatile("st.shared::cluster.b64 [%0], %1;" :: "r"(peerXd + (g0c * 6 + f) * 8), "l"(d0));
                asm volatile("st.shared::cluster.b64 [%0], %1;" :: "r"(peerXd + ((g0c + 1) * 6 + f) * 8), "l"(d1));
            }
        }
        if (cs == 0) {
            asm volatile("barrier.cluster.arrive.aligned;" ::: "memory");
            asm volatile("barrier.cluster.wait.aligned;" ::: "memory");
        } else {
            __syncthreads();
        }
    }

    // ---- head: relu(o @ lin_w + lin_b), pool over this block's 128 nodes ----
    {
        int k = t & 127, h2 = t >> 7;
        float lw0 = lin_w[k], lw1 = lin_w[128 + k], lw2 = lin_w[256 + k],
              lw3 = lin_w[384 + k], lw4 = lin_w[512 + k];
        float lb = lin_b[k];
        float s = 0.f;
        int n0 = c * 128 + h2 * 32;
        for (int n = n0; n < n0 + 32; n++) {
            const float* xr = &Xp[n * 5];
            float v = lb;
            v = fmaf(xr[0], lw0, v);
            v = fmaf(xr[1], lw1, v);
            v = fmaf(xr[2], lw2, v);
            v = fmaf(xr[3], lw3, v);
            v = fmaf(xr[4], lw4, v);
            s += fmaxf(v, 0.f);
        }
        Pool[h2 * 128 + k] = s;
    }
    __syncthreads();
    if (t < 128) {
        float p = Pool[t] + Pool[128 + t] + Pool[256 + t] + Pool[384 + t];
        if (c) {
            unsigned int lpp = (unsigned int)__cvta_generic_to_shared(&PoolP[t]);
            unsigned int rpp;
            asm("mapa.shared::cluster.u32 %0, %1, %2;" : "=r"(rpp) : "r"(lpp), "r"(prank));
            asm volatile("st.shared::cluster.f32 [%0], %1;" :: "r"(rpp), "f"(p));
        } else {
            Pool[t] = p;
        }
    }
    asm volatile("barrier.cluster.arrive.aligned;" ::: "memory");
    asm volatile("barrier.cluster.wait.aligned;" ::: "memory");
    if (c == 0 && t < 3) {
        float s = fc_b[t];
        for (int k2 = 0; k2 < 128; k2++)
            s = fmaf(Pool[k2] + PoolP[k2], fc_w[k2 * 3 + t], s);
        out[b * 3 + t] = s;
    }
}

// ---------------- launch ----------------
extern "C" void kernel_launch(void* const* d_in, const int* in_sizes, int n_in,
                              void* d_out, int out_size) {
    const float* x     = (const float*)d_in[0];
    const float* ewp   = (const float*)d_in[1];
    const float* a_uc  = (const float*)d_in[2];
    const float* b_uc  = (const float*)d_in[3];
    const float* u_pi  = (const float*)d_in[4];
    const float* u_rb  = (const float*)d_in[5];
    const float* lin_w = (const float*)d_in[6];
    const float* lin_b = (const float*)d_in[7];
    const float* fc_w  = (const float*)d_in[8];
    const float* fc_b  = (const float*)d_in[9];
    // d_in[10] = edge_index, d_in[11] = batch: structure is analytic, unused.
    float* out = (float*)d_out;

    static int attr_done = 0;
    if (!attr_done) {
        cudaFuncSetAttribute(conv_head_kernel,
                             cudaFuncAttributeMaxDynamicSharedMemorySize, SM_TOTAL);
        cudaFuncSetAttribute(gemm_kernel,
                             cudaFuncAttributeMaxDynamicSharedMemorySize, GEMM_SMEM);
        attr_done = 1;
    }

    float *S0, *SA, *S1, *S2, *P, *K1, *K2;
    cudaGetSymbolAddress((void**)&S0, g_S);
    SA = S0 + NE_;  S1 = S0 + 2 * NE_;  S2 = S0 + 3 * NE_;
    cudaGetSymbolAddress((void**)&P,  g_P);
    cudaGetSymbolAddress((void**)&K1, g_G);
    K2 = K1 + NE_;

    deg_scalar_kernel<<<33, 256>>>(ewp, a_uc, b_uc, u_pi, out);
    mats_kernel<<<N_, 256>>>(ewp, u_rb);
    gemm_kernel<<<128, 256, GEMM_SMEM>>>(S0, SA, P,  SA, S2, K2);   // P = S0*SA, K2 = SA*S2
    gemm_kernel<<<64, 256, GEMM_SMEM>>>(P, S1, K1,  P, S1, K1);     // K1 = P*S1
    conv_head_kernel<<<2 * B_, 512, SM_TOTAL>>>(x, lin_w, lin_b, fc_w, fc_b, out);
}

// round 6
// speedup vs baseline: 1.1391x; 1.1391x over previous
#include <cuda_runtime.h>
#include <math.h>

#define N_    256
#define B_    64
#define FIN   5
#define NE_   65536

// ---------------- scratch (no allocations allowed) ----------------
__device__ __align__(16) float g_S[4 * NE_];   // S0, SA, S1, S2  (0.1I + 0.45*M)
__device__ __align__(16) float g_P[NE_];       // P  = S0*SA
__device__ __align__(16) float g_G[NE_];       // K2 = SA*S2
__device__ float g_dis[N_];
__device__ float g_logits[3];

// ---------------- packed f32x2 helpers ----------------
static __device__ __forceinline__ unsigned long long ffma2(unsigned long long a,
                                                           unsigned long long b,
                                                           unsigned long long c) {
    unsigned long long d;
    asm("fma.rn.f32x2 %0, %1, %2, %3;" : "=l"(d) : "l"(a), "l"(b), "l"(c));
    return d;
}
static __device__ __forceinline__ unsigned long long fadd2(unsigned long long a,
                                                           unsigned long long b) {
    unsigned long long d;
    asm("add.rn.f32x2 %0, %1, %2;" : "=l"(d) : "l"(a), "l"(b));
    return d;
}
static __device__ __forceinline__ unsigned long long dup2(float v) {
    unsigned long long d;
    unsigned int u = __float_as_uint(v);
    asm("mov.b64 %0, {%1, %1};" : "=l"(d) : "r"(u));
    return d;
}
static __device__ __forceinline__ float2 unpack2(unsigned long long v) {
    unsigned int lo, hi;
    asm("mov.b64 {%0, %1}, %2;" : "=r"(lo), "=r"(hi) : "l"(v));
    return make_float2(__uint_as_float(lo), __uint_as_float(hi));
}

// ---------------- digamma (fp32) ----------------
static __device__ float digamma_f(float x) {
    float r = 0.0f;
    while (x < 8.0f) { r -= __fdividef(1.0f, x); x += 1.0f; }
    float f = __fdividef(1.0f, x * x);
    float s = f * (1.0f / 12.0f - f * (1.0f / 120.0f - f * (1.0f / 252.0f
            - f * (1.0f / 240.0f - f * (1.0f / 132.0f)))));
    return r + logf(x) - 0.5f / x - s;
}

// ---------------- kernel 1: degree/dis (32 blocks) + scalar block (block 32) --
__global__ void __launch_bounds__(256) deg_scalar_kernel(
        const float* __restrict__ ewp,
        const float* __restrict__ a_uc,
        const float* __restrict__ b_uc,
        const float* __restrict__ u_pi,
        float* __restrict__ out) {
    int b = blockIdx.x, t = threadIdx.x;
    if (b == 32) {   // scalar-only block (fp32)
        __shared__ float kld_s[3];
        if (t < 3) {
            int l = t;
            float au = a_uc[l]; if (au < -10.0f) au = -10.0f;
            float bu = b_uc[l]; if (bu < -10.0f) bu = -10.0f; if (bu > 50.0f) bu = 50.0f;
            float a = log1pf(expf(au));
            float bb = log1pf(expf(bu));
            float up = u_pi[l];
            up = fminf(fmaxf(up, 1e-6f), 1.0f - 1e-6f);
            float pi = powf(1.0f - powf(up, 1.0f / bb), 1.0f / a);
            g_logits[l] = logf(pi) - log1pf(-pi);
            out[193 + l] = pi;   // drop_rates
            const float euler = 0.577215664901532f;
            kld_s[l] = (1.0f - 0.8f / a) * (-euler - digamma_f(bb) - 1.0f / bb)
                     + logf(a * bb + 1e-10f) - logf(0.8f) - (bb - 1.0f) / bb;
        }
        __syncthreads();
        if (t == 0) out[192] = kld_s[0] + kld_s[1] + kld_s[2];   // kld_loss
        return;
    }
    // degree: warp w handles row r = b*8+w
    int w = t >> 5, l = t & 31;
    int r = b * 8 + w;
    float s = 0.f;
    #pragma unroll
    for (int jj = 0; jj < 8; jj++) {
        int j = l + jj * 32;
        int hi = max(r, j), lo = min(r, j);
        s += fabsf(ewp[(hi * (hi + 1)) / 2 + lo]);
    }
    #pragma unroll
    for (int o = 16; o > 0; o >>= 1) s += __shfl_xor_sync(0xffffffffu, s, o);
    if (l == 0) g_dis[r] = (s > 0.f) ? rsqrtf(s) : 0.f;
}

// ---------------- kernel 2: build S matrices (0.1I + 0.45*M) ------------------
__global__ void __launch_bounds__(256) mats_kernel(const float* __restrict__ ewp,
                                                   const float* __restrict__ u_rb) {
    int i = blockIdx.x, j = threadIdx.x;
    int r = max(i, j), c = min(i, j);
    float w = ewp[(r * (r + 1)) / 2 + c];
    float aij = g_dis[i] * w * g_dis[j];
    int e = i * N_ + j;
    float diag = (i == j) ? 0.1f : 0.0f;
    g_S[1 * NE_ + e] = 0.45f * aij + diag;                        // SA
    #pragma unroll
    for (int l = 0; l < 3; l++) {
        float ur = u_rb[l * NE_ + e];
        ur = fminf(fmaxf(ur, 1e-6f), 1.0f - 1e-6f);
        float tt = (g_logits[l] + __logf(ur) - __logf(1.0f - ur)) * (1.0f / 0.6f);
        float z = __fdividef(1.0f, 1.0f + __expf(-tt));
        int slot = (l == 0) ? 0 : (l + 1);                        // S0, S1, S2
        g_S[slot * NE_ + e] = 0.45f * z * aij + diag;
    }
}

// ---------------- kernel 3: dual 256x256x256 fp32 GEMM (tile 32x32) -----------
// grid 128: bx>>6 selects (A,B,C) triple; both GEMMs are independent.
// Inner loop staged 8-deep (8 LDS.32 A + 8 LDS.128 B, then 16 FFMA2) to break
// the per-k dependency chain.
#define GEMM_SMEM (33280 + 32768)
__global__ void __launch_bounds__(256) gemm_kernel(
        const float* __restrict__ A0, const float* __restrict__ B0, float* __restrict__ C0,
        const float* __restrict__ A1, const float* __restrict__ B1, float* __restrict__ C1) {
    extern __shared__ __align__(16) char gsm[];
    float*  As = (float*)gsm;                 // [32][260] padded
    float4* Bs = (float4*)(gsm + 33280);      // [256][8]

    int bx = blockIdx.x;
    int g = bx >> 6, tile = bx & 63;
    const float* A = g ? A1 : A0;
    const float* B = g ? B1 : B0;
    float*       C = g ? C1 : C0;
    int tr = tile >> 3, tc = tile & 7;
    int t = threadIdx.x;

    // load A strip (rows tr*32..+31, full K) and B strip (full K, cols tc*32..+31)
    #pragma unroll
    for (int it = 0; it < 8; it++) {
        int idx = t + it * 256;               // 2048 float4s each
        int r = idx >> 6, k4 = (idx & 63) << 2;
        *(float4*)&As[r * 260 + k4] = *(const float4*)&A[(tr * 32 + r) * 256 + k4];
        int rowk = idx >> 3, c4 = idx & 7;
        Bs[rowk * 8 + c4] = *(const float4*)&B[rowk * 256 + tc * 32 + c4 * 4];
    }
    __syncthreads();

    int r = t >> 3, c8 = t & 7;
    unsigned long long acc0 = 0ull, acc1 = 0ull;
    const float* arow = &As[r * 260];
    #pragma unroll 1
    for (int k0 = 0; k0 < 256; k0 += 8) {
        float a[8];
        ulonglong2 bv[8];
        #pragma unroll
        for (int u = 0; u < 8; u++) a[u] = arow[k0 + u];
        #pragma unroll
        for (int u = 0; u < 8; u++) bv[u] = *(const ulonglong2*)&Bs[(k0 + u) * 8 + c8];
        #pragma unroll
        for (int u = 0; u < 8; u++) {
            unsigned long long ad = dup2(a[u]);
            acc0 = ffma2(ad, bv[u].x, acc0);
            acc1 = ffma2(ad, bv[u].y, acc1);
        }
    }
    float2 a0 = unpack2(acc0), a1 = unpack2(acc1);
    float4 res = make_float4(a0.x, a0.y, a1.x, a1.y);
    *(float4*)&C[(tr * 32 + r) * 256 + tc * 32 + c8 * 4] = res;
}

// ---------------- kernel 4: 3-stage conv + head, clustered --------------------
// 128 blocks = (graph b = blockIdx.x>>1, column half c = blockIdx.x&1),
// cluster (2,1,1), 512 threads.
// stage 0: t = P^T x;  stage 1: x3 = relu(S1^T t);  stage 2: o = K2^T x3.
// K slabs stream via cp.async double-buffered halves; cluster exchanges X after
// stages 0 and 1.
#define SM_MTILE   0          // 2 * 128*128 f32 = 131072
#define SM_XD      131072     // 256*6 u64       = 12288
#define SM_XP      143360     // 256*5 f32       = 5120
#define SM_PS      148480     // 512*11 u64      = 45056
#define SM_POOL    193536     // 512 f32         = 2048
#define SM_POOLP   195584     // 128 f32         = 512
#define SM_TOTAL   196096

__global__ void __launch_bounds__(512, 1) __cluster_dims__(2, 1, 1)
conv_head_kernel(const float* __restrict__ x,
                 const float* __restrict__ lin_w, const float* __restrict__ lin_b,
                 const float* __restrict__ fc_w,  const float* __restrict__ fc_b,
                 float* __restrict__ out) {
    extern __shared__ __align__(16) char sm_[];
    float*              Mtile = (float*)(sm_ + SM_MTILE);
    unsigned long long* Xd    = (unsigned long long*)(sm_ + SM_XD);
    float*              Xp    = (float*)(sm_ + SM_XP);
    unsigned long long* Ps    = (unsigned long long*)(sm_ + SM_PS);
    float*              Pool  = (float*)(sm_ + SM_POOL);
    float*              PoolP = (float*)(sm_ + SM_POOLP);

    const int t  = threadIdx.x;
    const int j4 = t & 31;              // 4-col group within the 128-col slab
    const int q  = t >> 5;              // 0..15 K-split (8 rows per half)
    const int b  = blockIdx.x >> 1;
    const int c  = blockIdx.x & 1;      // == cluster rank
    const unsigned prank = (unsigned)(c ^ 1);

    const float* stage_mat[3] = { g_P, g_S + 2 * NE_, g_G };

    auto issue_half = [&](const float* gsrc, float* stile) {
        #pragma unroll
        for (int k = 0; k < 8; k++) {
            int o = (k << 9) + t;
            int row = o >> 5, seg = (o & 31) << 2;
            const float* src = gsrc + row * 256 + seg;
            unsigned int dst = (unsigned int)__cvta_generic_to_shared(&stile[row * 128 + seg]);
            asm volatile("cp.async.cg.shared.global [%0], [%1], 16;" :: "r"(dst), "l"(src));
        }
        asm volatile("cp.async.commit_group;" ::: "memory");
    };

    // prefetch stage 0 (P)
    {
        const float* g0 = stage_mat[0] + c * 128;
        issue_half(g0, Mtile);
        issue_half(g0 + 128 * 256, Mtile + 16384);
    }

    // load this graph's X
    {
        const float* xb = x + b * (N_ * FIN);
        for (int idx = t; idx < N_ * FIN; idx += 512) {
            float v = xb[idx];
            int i = idx / 5, f = idx - i * 5;
            Xp[idx] = v;
            Xd[i * 6 + f] = dup2(v);
        }
    }

    unsigned int peerXp, peerXd;
    {
        unsigned int lxp = (unsigned int)__cvta_generic_to_shared(Xp);
        unsigned int lxd = (unsigned int)__cvta_generic_to_shared(Xd);
        asm("mapa.shared::cluster.u32 %0, %1, %2;" : "=r"(peerXp) : "r"(lxp), "r"(prank));
        asm("mapa.shared::cluster.u32 %0, %1, %2;" : "=r"(peerXd) : "r"(lxd), "r"(prank));
    }

    unsigned long long accA[FIN], accB[FIN];
    const int qq8 = q * 8;

    #pragma unroll 1
    for (int cs = 0; cs < 3; cs++) {
        #pragma unroll
        for (int f = 0; f < FIN; f++) { accA[f] = 0ull; accB[f] = 0ull; }

        asm volatile("cp.async.wait_group 1;" ::: "memory");
        __syncthreads();

        #pragma unroll
        for (int r_ = 0; r_ < 8; r_++) {
            int row = qq8 + r_;
            ulonglong2 mv = *(const ulonglong2*)&Mtile[row * 128 + j4 * 4];
            const unsigned long long* xr = &Xd[row * 6];
            ulonglong2 x01 = *(const ulonglong2*)xr;
            ulonglong2 x23 = *(const ulonglong2*)(xr + 2);
            unsigned long long x4 = xr[4];
            accA[0] = ffma2(mv.x, x01.x, accA[0]);  accB[0] = ffma2(mv.y, x01.x, accB[0]);
            accA[1] = ffma2(mv.x, x01.y, accA[1]);  accB[1] = ffma2(mv.y, x01.y, accB[1]);
            accA[2] = ffma2(mv.x, x23.x, accA[2]);  accB[2] = ffma2(mv.y, x23.x, accB[2]);
            accA[3] = ffma2(mv.x, x23.y, accA[3]);  accB[3] = ffma2(mv.y, x23.y, accB[3]);
            accA[4] = ffma2(mv.x, x4,    accA[4]);  accB[4] = ffma2(mv.y, x4,    accB[4]);
        }

        asm volatile("cp.async.wait_group 0;" ::: "memory");
        __syncthreads();

        #pragma unroll
        for (int r_ = 0; r_ < 8; r_++) {
            int row = qq8 + r_;
            ulonglong2 mv = *(const ulonglong2*)&Mtile[16384 + row * 128 + j4 * 4];
            const unsigned long long* xr = &Xd[(128 + row) * 6];
            ulonglong2 x01 = *(const ulonglong2*)xr;
            ulonglong2 x23 = *(const ulonglong2*)(xr + 2);
            unsigned long long x4 = xr[4];
            accA[0] = ffma2(mv.x, x01.x, accA[0]);  accB[0] = ffma2(mv.y, x01.x, accB[0]);
            accA[1] = ffma2(mv.x, x01.y, accA[1]);  accB[1] = ffma2(mv.y, x01.y, accB[1]);
            accA[2] = ffma2(mv.x, x23.x, accA[2]);  accB[2] = ffma2(mv.y, x23.x, accB[2]);
            accA[3] = ffma2(mv.x, x23.y, accA[3]);  accB[3] = ffma2(mv.y, x23.y, accB[3]);
            accA[4] = ffma2(mv.x, x4,    accA[4]);  accB[4] = ffma2(mv.y, x4,    accB[4]);
        }

        {
            int base = (q * 32 + j4) * 11;
            #pragma unroll
            for (int f = 0; f < FIN; f++) { Ps[base + f] = accA[f]; Ps[base + 5 + f] = accB[f]; }
        }
        __syncthreads();   // done reading Mtile & writing Ps

        // prefetch next stage's matrix
        if (cs < 2) {
            const float* gsrc = stage_mat[cs + 1] + c * 128;
            issue_half(gsrc, Mtile);
            issue_half(gsrc + 128 * 256, Mtile + 16384);
        }

        // combine 16 K-splits; relu on stage 1; peer exchange on stages 0,1
        if (t < 320) {
            int f = t % 5, pc = t / 5;
            int j4c = pc >> 1, a = pc & 1;
            unsigned long long s = Ps[j4c * 11 + a * 5 + f];
            #pragma unroll
            for (int qq = 1; qq < 16; qq++)
                s = fadd2(s, Ps[(qq * 32 + j4c) * 11 + a * 5 + f]);
            float2 sv = unpack2(s);
            float y0 = sv.x, y1 = sv.y;
            if (cs == 1) { y0 = fmaxf(y0, 0.f); y1 = fmaxf(y1, 0.f); }
            int g0c = c * 128 + 4 * j4c + 2 * a;
            Xp[g0c * 5 + f] = y0;  Xp[(g0c + 1) * 5 + f] = y1;
            if (cs < 2) {
                unsigned long long d0 = dup2(y0), d1 = dup2(y1);
                Xd[g0c * 6 + f] = d0;  Xd[(g0c + 1) * 6 + f] = d1;
                asm volatile("st.shared::cluster.f32 [%0], %1;" :: "r"(peerXp + (g0c * 5 + f) * 4), "f"(y0));
                asm volatile("st.shared::cluster.f32 [%0], %1;" :: "r"(peerXp + ((g0c + 1) * 5 + f) * 4), "f"(y1));
                asm volatile("st.shared::cluster.b64 [%0], %1;" :: "r"(peerXd + (g0c * 6 + f) * 8), "l"(d0));
                asm volatile("st.shared::cluster.b64 [%0], %1;" :: "r"(peerXd + ((g0c + 1) * 6 + f) * 8), "l"(d1));
            }
        }
        if (cs < 2) {
            asm volatile("barrier.cluster.arrive.aligned;" ::: "memory");
            asm volatile("barrier.cluster.wait.aligned;" ::: "memory");
        } else {
            __syncthreads();
        }
    }

    // ---- head: relu(o @ lin_w + lin_b), pool over this block's 128 nodes ----
    {
        int k = t & 127, h2 = t >> 7;
        float lw0 = lin_w[k], lw1 = lin_w[128 + k], lw2 = lin_w[256 + k],
              lw3 = lin_w[384 + k], lw4 = lin_w[512 + k];
        float lb = lin_b[k];
        float s = 0.f;
        int n0 = c * 128 + h2 * 32;
        for (int n = n0; n < n0 + 32; n++) {
            const float* xr = &Xp[n * 5];
            float v = lb;
            v = fmaf(xr[0], lw0, v);
            v = fmaf(xr[1], lw1, v);
            v = fmaf(xr[2], lw2, v);
            v = fmaf(xr[3], lw3, v);
            v = fmaf(xr[4], lw4, v);
            s += fmaxf(v, 0.f);
        }
        Pool[h2 * 128 + k] = s;
    }
    __syncthreads();
    if (t < 128) {
        float p = Pool[t] + Pool[128 + t] + Pool[256 + t] + Pool[384 + t];
        if (c) {
            unsigned int lpp = (unsigned int)__cvta_generic_to_shared(&PoolP[t]);
            unsigned int rpp;
            asm("mapa.shared::cluster.u32 %0, %1, %2;" : "=r"(rpp) : "r"(lpp), "r"(prank));
            asm volatile("st.shared::cluster.f32 [%0], %1;" :: "r"(rpp), "f"(p));
        } else {
            Pool[t] = p;
        }
    }
    asm volatile("barrier.cluster.arrive.aligned;" ::: "memory");
    asm volatile("barrier.cluster.wait.aligned;" ::: "memory");
    if (c == 0 && t < 3) {
        float s = fc_b[t];
        for (int k2 = 0; k2 < 128; k2++)
            s = fmaf(Pool[k2] + PoolP[k2], fc_w[k2 * 3 + t], s);
        out[b * 3 + t] = s;
    }
}

// ---------------- launch ----------------
extern "C" void kernel_launch(void* const* d_in, const int* in_sizes, int n_in,
                              void* d_out, int out_size) {
    const float* x     = (const float*)d_in[0];
    const float* ewp   = (const float*)d_in[1];
    const float* a_uc  = (const float*)d_in[2];
    const float* b_uc  = (const float*)d_in[3];
    const float* u_pi  = (const float*)d_in[4];
    const float* u_rb  = (const float*)d_in[5];
    const float* lin_w = (const float*)d_in[6];
    const float* lin_b = (const float*)d_in[7];
    const float* fc_w  = (const float*)d_in[8];
    const float* fc_b  = (const float*)d_in[9];
    // d_in[10] = edge_index, d_in[11] = batch: structure is analytic, unused.
    float* out = (float*)d_out;

    cudaFuncSetAttribute(conv_head_kernel,
                         cudaFuncAttributeMaxDynamicSharedMemorySize, SM_TOTAL);
    cudaFuncSetAttribute(gemm_kernel,
                         cudaFuncAttributeMaxDynamicSharedMemorySize, GEMM_SMEM);

    float *S0, *SA, *S2, *P, *K2;
    cudaGetSymbolAddress((void**)&S0, g_S);
    SA = S0 + NE_;  S2 = S0 + 3 * NE_;
    cudaGetSymbolAddress((void**)&P,  g_P);
    cudaGetSymbolAddress((void**)&K2, g_G);

    deg_scalar_kernel<<<33, 256>>>(ewp, a_uc, b_uc, u_pi, out);
    mats_kernel<<<N_, 256>>>(ewp, u_rb);
    gemm_kernel<<<128, 256, GEMM_SMEM>>>(S0, SA, P,  SA, S2, K2);  // P = S0*SA, K2 = SA*S2
    conv_head_kernel<<<2 * B_, 512, SM_TOTAL>>>(x, lin_w, lin_b, fc_w, fc_b, out);
}